// round 3
// baseline (speedup 1.0000x reference)
#include <cuda_runtime.h>
#include <cuda_bf16.h>
#include <cstdint>

// BitLinear158 on sm_103 (base ISA only — no tcgen05; harness ptxas targets
// sm_103 without the 'a' feature set):
//   LN -> int8 absmax quant -> int8 IMMA GEMM (exact s32 accum)
//   -> xs*ws scale epilogue -> LN
// tokens = 16384, DIN = DOUT = 2048

#define NTOK   16384
#define DIN    2048
#define DOUT   2048

#define BMT    128           // GEMM M tile
#define BNT    128           // GEMM N tile
#define BKT    128           // GEMM K tile (int8 bytes)
#define NKT    (DIN / BKT)   // 16 K-chunks
#define STAGES 4
#define ATILE  16384         // 128 rows * 128 B
#define STAGE_BYTES (2 * ATILE)
#define TILES_OFF   2048
#define GEMM_SMEM   (TILES_OFF + STAGES * STAGE_BYTES)   // 133120

// Pre-tiled, pre-swizzled int8 scratch (SMEM tile image; one bulk copy/stage)
__device__ __align__(1024) unsigned char g_Aq8[(size_t)NTOK * DIN];  // 32 MB
__device__ __align__(1024) unsigned char g_Wq8[(size_t)DOUT * DIN];  //  4 MB
__device__ float g_xscale[NTOK];

// ---------------- PTX helpers ----------------
__device__ __forceinline__ uint32_t smem_u32(const void* p) {
    uint32_t a;
    asm("{ .reg .u64 t; cvta.to.shared.u64 t, %1; cvt.u32.u64 %0, t; }"
        : "=r"(a) : "l"(p));
    return a;
}
__device__ __forceinline__ uint64_t gptr(const void* p) {
    uint64_t a;
    asm("cvta.to.global.u64 %0, %1;" : "=l"(a) : "l"(p));
    return a;
}
__device__ __forceinline__ void mbar_init(uint32_t mbar, uint32_t count) {
    asm volatile("mbarrier.init.shared.b64 [%0], %1;" :: "r"(mbar), "r"(count) : "memory");
}
__device__ __forceinline__ void mbar_expect_tx(uint32_t mbar, uint32_t bytes) {
    asm volatile("mbarrier.arrive.expect_tx.shared.b64 _, [%0], %1;"
                 :: "r"(mbar), "r"(bytes) : "memory");
}
__device__ __forceinline__ void mbar_arrive(uint32_t mbar) {
    asm volatile("mbarrier.arrive.shared.b64 _, [%0];" :: "r"(mbar) : "memory");
}
__device__ __forceinline__ void wait_parity(uint32_t mbar, uint32_t phase) {
    asm volatile(
        "{\n\t.reg .pred P;\n\t"
        "WL_%=:\n\t"
        "mbarrier.try_wait.parity.acquire.cta.shared::cta.b64 P, [%0], %1, 0x989680;\n\t"
        "@P bra.uni WD_%=;\n\t"
        "bra.uni WL_%=;\n\t"
        "WD_%=:\n\t}"
        :: "r"(mbar), "r"(phase) : "memory");
}
__device__ __forceinline__ void bulk_g2s(uint32_t dst, uint64_t src_global,
                                         uint32_t bytes, uint32_t mbar) {
    asm volatile(
        "cp.async.bulk.shared::cluster.global.mbarrier::complete_tx::bytes "
        "[%0], [%1], %2, [%3];"
        :: "r"(dst), "l"(src_global), "r"(bytes), "r"(mbar) : "memory");
}
#define LDSM4(d, addr) \
    asm volatile("ldmatrix.sync.aligned.m8n8.x4.shared.b16 {%0,%1,%2,%3}, [%4];" \
                 : "=r"((d)[0]), "=r"((d)[1]), "=r"((d)[2]), "=r"((d)[3])       \
                 : "r"(addr))
#define MMA_S8(C, A, b0, b1) \
    asm volatile("mma.sync.aligned.m16n8k32.row.col.s32.s8.s8.s32 "             \
                 "{%0,%1,%2,%3}, {%4,%5,%6,%7}, {%8,%9}, {%0,%1,%2,%3};"        \
                 : "+r"((C)[0]), "+r"((C)[1]), "+r"((C)[2]), "+r"((C)[3])       \
                 : "r"((A)[0]), "r"((A)[1]), "r"((A)[2]), "r"((A)[3]),          \
                   "r"(b0), "r"(b1))

__device__ __forceinline__ float warp_sum(float v) {
#pragma unroll
    for (int o = 16; o > 0; o >>= 1) v += __shfl_xor_sync(0xFFFFFFFFu, v, o);
    return v;
}
__device__ __forceinline__ float warp_max(float v) {
#pragma unroll
    for (int o = 16; o > 0; o >>= 1) v = fmaxf(v, __shfl_xor_sync(0xFFFFFFFFu, v, o));
    return v;
}
__device__ __forceinline__ unsigned pack4(int a, int b, int c, int d) {
    return (unsigned)(a & 0xFF) | ((unsigned)(b & 0xFF) << 8) |
           ((unsigned)(c & 0xFF) << 16) | ((unsigned)(d & 0xFF) << 24);
}

// ---------------- Kernel 1: input LN + absmax int8 quant -> tiled A scratch
__global__ __launch_bounds__(256) void k_ln_quant(const float* __restrict__ x) {
    const int t = blockIdx.x;
    const int tid = threadIdx.x;
    const int lane = tid & 31, wid = tid >> 5;

    const float4* rp = reinterpret_cast<const float4*>(x + (size_t)t * DIN);
    float4 p0 = rp[2 * tid], p1 = rp[2 * tid + 1];
    float v[8] = {p0.x, p0.y, p0.z, p0.w, p1.x, p1.y, p1.z, p1.w};

    float s = 0.f, sq = 0.f;
#pragma unroll
    for (int i = 0; i < 8; ++i) { s += v[i]; sq += v[i] * v[i]; }

    __shared__ float r1[8], r2[8];
    __shared__ float sh_mu, sh_rstd, sh_inv, sh_s;
    s = warp_sum(s); sq = warp_sum(sq);
    if (lane == 0) { r1[wid] = s; r2[wid] = sq; }
    __syncthreads();
    if (tid == 0) {
        float a = 0.f, b = 0.f;
#pragma unroll
        for (int i = 0; i < 8; ++i) { a += r1[i]; b += r2[i]; }
        float mu = a * (1.0f / DIN);
        float var = b * (1.0f / DIN) - mu * mu;
        sh_mu = mu;
        sh_rstd = rsqrtf(var + 1e-5f);
    }
    __syncthreads();
    const float mu = sh_mu, rstd = sh_rstd;
    float amax = 0.f;
#pragma unroll
    for (int i = 0; i < 8; ++i) {
        v[i] = (v[i] - mu) * rstd;
        amax = fmaxf(amax, fabsf(v[i]));
    }
    amax = warp_max(amax);
    if (lane == 0) r1[wid] = amax;
    __syncthreads();
    if (tid == 0) {
        float m = r1[0];
#pragma unroll
        for (int i = 1; i < 8; ++i) m = fmaxf(m, r1[i]);
        float sc = fmaxf(m, 1e-5f) * (1.0f / 127.0f);
        sh_s = sc;
        sh_inv = 1.0f / sc;
    }
    __syncthreads();
    const float inv = sh_inv;

    int q[8];
#pragma unroll
    for (int i = 0; i < 8; ++i)
        q[i] = (int)fminf(fmaxf(rintf(v[i] * inv), -127.f), 127.f);
    uint2 st;
    st.x = pack4(q[0], q[1], q[2], q[3]);
    st.y = pack4(q[4], q[5], q[6], q[7]);

    // token t -> tile (mt), row r; element bytes 8*tid..8*tid+7
    const int mt = t >> 7, r = t & 127;
    const int kc = tid >> 4, c = (tid >> 1) & 7, half = tid & 1;
    size_t off = ((size_t)(mt * NKT + kc) * 128 + r) * 128 +
                 (size_t)((c ^ (r & 7)) << 4) + (size_t)half * 8;
    *reinterpret_cast<uint2*>(g_Aq8 + off) = st;
    if (tid == 0) g_xscale[t] = sh_s;
}

// ---------------- Kernel 2: ternary int32 -> int8, same tiled layout
__global__ __launch_bounds__(256) void k_wconv(const int* __restrict__ wt) {
    const int n = blockIdx.x;
    const int tid = threadIdx.x;
    const int4* rp = reinterpret_cast<const int4*>(wt + (size_t)n * DIN);
    int4 a = rp[2 * tid], b = rp[2 * tid + 1];
    uint2 st;
    st.x = pack4(a.x, a.y, a.z, a.w);
    st.y = pack4(b.x, b.y, b.z, b.w);
    const int nt = n >> 7, r = n & 127;
    const int kc = tid >> 4, c = (tid >> 1) & 7, half = tid & 1;
    size_t off = ((size_t)(nt * NKT + kc) * 128 + r) * 128 +
                 (size_t)((c ^ (r & 7)) << 4) + (size_t)half * 8;
    *reinterpret_cast<uint2*>(g_Wq8 + off) = st;
}

// ---------------- Kernel 3: int8 IMMA GEMM, 128x128x128 tiles, 4-stage bulk pipe
__global__ __launch_bounds__(256, 1) void k_gemm(const float* __restrict__ wscale,
                                                 float* __restrict__ out) {
    extern __shared__ unsigned char smem[];
    const uint32_t sb = smem_u32(smem);
    const int tid = threadIdx.x, lane = tid & 31, wid = tid >> 5;
    const int bn = blockIdx.x, bm = blockIdx.y;

    // stage scales: ws at +512, xs at +1024
    if (tid < 128) {
        reinterpret_cast<float*>(smem + 512)[tid]  = wscale[bn * BNT + tid];
        reinterpret_cast<float*>(smem + 1024)[tid] = g_xscale[bm * BMT + tid];
    }
    if (tid == 0) {
#pragma unroll
        for (int s = 0; s < STAGES; ++s) {
            mbar_init(sb + 8 + 16 * s, 1);      // full[s]: tx-based
            mbar_init(sb + 16 + 16 * s, 256);   // empty[s]: all threads arrive
        }
        asm volatile("fence.proxy.async.shared::cta;" ::: "memory");
    }
    __syncthreads();

    const uint64_t gA = gptr(g_Aq8) + (uint64_t)bm * ((uint64_t)NKT * ATILE);
    const uint64_t gB = gptr(g_Wq8) + (uint64_t)bn * ((uint64_t)NKT * ATILE);

    if (tid == 0) {
#pragma unroll
        for (int s = 0; s < STAGES; ++s) {
            const uint32_t fb = sb + 8 + 16 * s;
            mbar_expect_tx(fb, STAGE_BYTES);
            bulk_g2s(sb + TILES_OFF + s * STAGE_BYTES,
                     gA + (uint64_t)s * ATILE, ATILE, fb);
            bulk_g2s(sb + TILES_OFF + s * STAGE_BYTES + ATILE,
                     gB + (uint64_t)s * ATILE, ATILE, fb);
        }
    }

    // per-lane constants (warp grid 2x4: wm in M, wn in N)
    const int wm = wid >> 2, wn = wid & 3;
    const int xr = lane & 7;           // swizzle XOR (row & 7)
    const int hiA = lane >> 4;         // A: lanes 16-31 take the +16B chunk
    const int hiB = (lane >> 3) & 1;   // B: lanes 8-15 / 24-31 take +16B
    int rA[4], rB[2];
#pragma unroll
    for (int mt = 0; mt < 4; ++mt) rA[mt] = wm * 64 + mt * 16 + (lane & 15);
#pragma unroll
    for (int p = 0; p < 2; ++p)
        rB[p] = wn * 32 + p * 16 + ((lane >> 4) << 3) + (lane & 7);

    int C[4][4][4];
#pragma unroll
    for (int i = 0; i < 4; ++i)
#pragma unroll
        for (int j2 = 0; j2 < 4; ++j2)
#pragma unroll
            for (int k = 0; k < 4; ++k) C[i][j2][k] = 0;

    for (int kt = 0; kt < NKT; ++kt) {
        const int s = kt & (STAGES - 1), j = kt >> 2;
        const uint32_t fb = sb + 8 + 16 * s;
        const uint32_t eb = sb + 16 + 16 * s;
        wait_parity(fb, (uint32_t)(j & 1));
        const uint32_t aS = sb + TILES_OFF + s * STAGE_BYTES;
        const uint32_t bS = aS + ATILE;

#pragma unroll
        for (int ks = 0; ks < 4; ++ks) {    // 4 x k32 substeps per 128B chunk
            uint32_t afr[4][4], bfr[2][4];
#pragma unroll
            for (int mt = 0; mt < 4; ++mt) {
                uint32_t addr = aS + rA[mt] * 128 +
                                (uint32_t)(((ks * 2 + hiA) ^ xr) << 4);
                LDSM4(afr[mt], addr);
            }
#pragma unroll
            for (int p = 0; p < 2; ++p) {
                uint32_t addr = bS + rB[p] * 128 +
                                (uint32_t)(((ks * 2 + hiB) ^ xr) << 4);
                LDSM4(bfr[p], addr);
            }
#pragma unroll
            for (int mt = 0; mt < 4; ++mt)
#pragma unroll
                for (int nt = 0; nt < 4; ++nt)
                    MMA_S8(C[mt][nt], afr[mt],
                           bfr[nt >> 1][(nt & 1) * 2],
                           bfr[nt >> 1][(nt & 1) * 2 + 1]);
        }
        mbar_arrive(eb);
        if (tid == 0 && kt + STAGES < NKT) {
            wait_parity(eb, (uint32_t)(j & 1));   // all consumers done with s
            mbar_expect_tx(fb, STAGE_BYTES);
            bulk_g2s(aS, gA + (uint64_t)(kt + STAGES) * ATILE, ATILE, fb);
            bulk_g2s(bS, gB + (uint64_t)(kt + STAGES) * ATILE, ATILE, fb);
        }
    }

    // epilogue: scale by xs[m] * ws[n], f32 stores
    const float* sws = reinterpret_cast<const float*>(smem + 512);
    const float* sxs = reinterpret_cast<const float*>(smem + 1024);
#pragma unroll
    for (int mt = 0; mt < 4; ++mt) {
        const int r0 = wm * 64 + mt * 16 + (lane >> 2);
        const float xs0 = sxs[r0], xs1 = sxs[r0 + 8];
#pragma unroll
        for (int nt = 0; nt < 4; ++nt) {
            const int col = wn * 32 + nt * 8 + ((lane & 3) << 1);
            const float w0 = sws[col], w1 = sws[col + 1];
            size_t base = (size_t)(bm * BMT + r0) * DOUT + (size_t)(bn * BNT + col);
            float2 o0, o1;
            o0.x = (float)C[mt][nt][0] * xs0 * w0;
            o0.y = (float)C[mt][nt][1] * xs0 * w1;
            o1.x = (float)C[mt][nt][2] * xs1 * w0;
            o1.y = (float)C[mt][nt][3] * xs1 * w1;
            *reinterpret_cast<float2*>(out + base) = o0;
            *reinterpret_cast<float2*>(out + base + 8 * DOUT) = o1;
        }
    }
}

// ---------------- Kernel 4: output LayerNorm in place
__global__ __launch_bounds__(256) void k_ln_out(float* __restrict__ out) {
    const int t = blockIdx.x;
    const int tid = threadIdx.x;
    const int lane = tid & 31, wid = tid >> 5;

    float4* rp = reinterpret_cast<float4*>(out + (size_t)t * DOUT);
    float4 p0 = rp[2 * tid], p1 = rp[2 * tid + 1];
    float v[8] = {p0.x, p0.y, p0.z, p0.w, p1.x, p1.y, p1.z, p1.w};

    float s = 0.f, sq = 0.f;
#pragma unroll
    for (int i = 0; i < 8; ++i) { s += v[i]; sq += v[i] * v[i]; }

    __shared__ float r1[8], r2[8];
    __shared__ float sh_mu, sh_rstd;
    s = warp_sum(s); sq = warp_sum(sq);
    if (lane == 0) { r1[wid] = s; r2[wid] = sq; }
    __syncthreads();
    if (tid == 0) {
        float a = 0.f, b = 0.f;
#pragma unroll
        for (int i = 0; i < 8; ++i) { a += r1[i]; b += r2[i]; }
        float mu = a * (1.0f / DOUT);
        float var = b * (1.0f / DOUT) - mu * mu;
        sh_mu = mu;
        sh_rstd = rsqrtf(var + 1e-5f);
    }
    __syncthreads();
    const float mu = sh_mu, rstd = sh_rstd;
    float4 q0, q1;
    q0.x = (v[0] - mu) * rstd; q0.y = (v[1] - mu) * rstd;
    q0.z = (v[2] - mu) * rstd; q0.w = (v[3] - mu) * rstd;
    q1.x = (v[4] - mu) * rstd; q1.y = (v[5] - mu) * rstd;
    q1.z = (v[6] - mu) * rstd; q1.w = (v[7] - mu) * rstd;
    rp[2 * tid] = q0; rp[2 * tid + 1] = q1;
}

extern "C" void kernel_launch(void* const* d_in, const int* in_sizes, int n_in,
                              void* d_out, int out_size) {
    const float* x = (const float*)d_in[0];
    const int* wt = (const int*)d_in[1];
    const float* ws = (const float*)d_in[2];
    float* out = (float*)d_out;

    cudaFuncSetAttribute(k_gemm, cudaFuncAttributeMaxDynamicSharedMemorySize,
                         GEMM_SMEM);

    k_ln_quant<<<NTOK, 256>>>(x);
    k_wconv<<<DOUT, 256>>>(wt);
    dim3 g(DOUT / BNT, NTOK / BMT);
    k_gemm<<<g, 256, GEMM_SMEM>>>(ws, out);
    k_ln_out<<<NTOK, 256>>>(out);
}

// round 5
// speedup vs baseline: 1.0348x; 1.0348x over previous
#include <cuda_runtime.h>
#include <cuda_bf16.h>
#include <cstdint>

// BitLinear158 on sm_103 (base ISA — harness ptxas rejects tcgen05):
//   LN -> int8 absmax quant -> int8 IMMA GEMM (exact s32 accum)
//   -> xs*ws scale epilogue -> LN
// R4 experiment (re-run): STAGES 4->3 (smem 133->100 KB) +
// __launch_bounds__(256,2) => 2 CTAs/SM (4 warps/SMSP) to discriminate
// stall-bound (H2) vs issue-rate-bound (H1) GEMM.

#define NTOK   16384
#define DIN    2048
#define DOUT   2048

#define BMT    128
#define BNT    128
#define BKT    128
#define NKT    (DIN / BKT)   // 16 K-chunks
#define STAGES 3
#define ATILE  16384         // 128 rows * 128 B
#define STAGE_BYTES (2 * ATILE)
#define TILES_OFF   2048
#define GEMM_SMEM   (TILES_OFF + STAGES * STAGE_BYTES)   // 100352 B -> 2 CTA/SM

__device__ __align__(1024) unsigned char g_Aq8[(size_t)NTOK * DIN];  // 32 MB
__device__ __align__(1024) unsigned char g_Wq8[(size_t)DOUT * DIN];  //  4 MB
__device__ float g_xscale[NTOK];

// ---------------- PTX helpers ----------------
__device__ __forceinline__ uint32_t smem_u32(const void* p) {
    uint32_t a;
    asm("{ .reg .u64 t; cvta.to.shared.u64 t, %1; cvt.u32.u64 %0, t; }"
        : "=r"(a) : "l"(p));
    return a;
}
__device__ __forceinline__ uint64_t gptr(const void* p) {
    uint64_t a;
    asm("cvta.to.global.u64 %0, %1;" : "=l"(a) : "l"(p));
    return a;
}
__device__ __forceinline__ void mbar_init(uint32_t mbar, uint32_t count) {
    asm volatile("mbarrier.init.shared.b64 [%0], %1;" :: "r"(mbar), "r"(count) : "memory");
}
__device__ __forceinline__ void mbar_expect_tx(uint32_t mbar, uint32_t bytes) {
    asm volatile("mbarrier.arrive.expect_tx.shared.b64 _, [%0], %1;"
                 :: "r"(mbar), "r"(bytes) : "memory");
}
__device__ __forceinline__ void mbar_arrive(uint32_t mbar) {
    asm volatile("mbarrier.arrive.shared.b64 _, [%0];" :: "r"(mbar) : "memory");
}
__device__ __forceinline__ void wait_parity(uint32_t mbar, uint32_t phase) {
    asm volatile(
        "{\n\t.reg .pred P;\n\t"
        "WL_%=:\n\t"
        "mbarrier.try_wait.parity.acquire.cta.shared::cta.b64 P, [%0], %1, 0x989680;\n\t"
        "@P bra.uni WD_%=;\n\t"
        "bra.uni WL_%=;\n\t"
        "WD_%=:\n\t}"
        :: "r"(mbar), "r"(phase) : "memory");
}
__device__ __forceinline__ void bulk_g2s(uint32_t dst, uint64_t src_global,
                                         uint32_t bytes, uint32_t mbar) {
    asm volatile(
        "cp.async.bulk.shared::cluster.global.mbarrier::complete_tx::bytes "
        "[%0], [%1], %2, [%3];"
        :: "r"(dst), "l"(src_global), "r"(bytes), "r"(mbar) : "memory");
}
#define LDSM4(d, addr) \
    asm volatile("ldmatrix.sync.aligned.m8n8.x4.shared.b16 {%0,%1,%2,%3}, [%4];" \
                 : "=r"((d)[0]), "=r"((d)[1]), "=r"((d)[2]), "=r"((d)[3])       \
                 : "r"(addr))
#define MMA_S8(C, A, b0, b1) \
    asm volatile("mma.sync.aligned.m16n8k32.row.col.s32.s8.s8.s32 "             \
                 "{%0,%1,%2,%3}, {%4,%5,%6,%7}, {%8,%9}, {%0,%1,%2,%3};"        \
                 : "+r"((C)[0]), "+r"((C)[1]), "+r"((C)[2]), "+r"((C)[3])       \
                 : "r"((A)[0]), "r"((A)[1]), "r"((A)[2]), "r"((A)[3]),          \
                   "r"(b0), "r"(b1))

__device__ __forceinline__ float warp_sum(float v) {
#pragma unroll
    for (int o = 16; o > 0; o >>= 1) v += __shfl_xor_sync(0xFFFFFFFFu, v, o);
    return v;
}
__device__ __forceinline__ float warp_max(float v) {
#pragma unroll
    for (int o = 16; o > 0; o >>= 1) v = fmaxf(v, __shfl_xor_sync(0xFFFFFFFFu, v, o));
    return v;
}
__device__ __forceinline__ unsigned pack4(int a, int b, int c, int d) {
    return (unsigned)(a & 0xFF) | ((unsigned)(b & 0xFF) << 8) |
           ((unsigned)(c & 0xFF) << 16) | ((unsigned)(d & 0xFF) << 24);
}

// ---------------- Kernel 1: input LN + absmax int8 quant -> tiled A scratch
__global__ __launch_bounds__(256) void k_ln_quant(const float* __restrict__ x) {
    const int t = blockIdx.x;
    const int tid = threadIdx.x;
    const int lane = tid & 31, wid = tid >> 5;

    const float4* rp = reinterpret_cast<const float4*>(x + (size_t)t * DIN);
    float4 p0 = rp[2 * tid], p1 = rp[2 * tid + 1];
    float v[8] = {p0.x, p0.y, p0.z, p0.w, p1.x, p1.y, p1.z, p1.w};

    float s = 0.f, sq = 0.f;
#pragma unroll
    for (int i = 0; i < 8; ++i) { s += v[i]; sq += v[i] * v[i]; }

    __shared__ float r1[8], r2[8];
    __shared__ float sh_mu, sh_rstd, sh_inv, sh_s;
    s = warp_sum(s); sq = warp_sum(sq);
    if (lane == 0) { r1[wid] = s; r2[wid] = sq; }
    __syncthreads();
    if (tid == 0) {
        float a = 0.f, b = 0.f;
#pragma unroll
        for (int i = 0; i < 8; ++i) { a += r1[i]; b += r2[i]; }
        float mu = a * (1.0f / DIN);
        float var = b * (1.0f / DIN) - mu * mu;
        sh_mu = mu;
        sh_rstd = rsqrtf(var + 1e-5f);
    }
    __syncthreads();
    const float mu = sh_mu, rstd = sh_rstd;
    float amax = 0.f;
#pragma unroll
    for (int i = 0; i < 8; ++i) {
        v[i] = (v[i] - mu) * rstd;
        amax = fmaxf(amax, fabsf(v[i]));
    }
    amax = warp_max(amax);
    if (lane == 0) r1[wid] = amax;
    __syncthreads();
    if (tid == 0) {
        float m = r1[0];
#pragma unroll
        for (int i = 1; i < 8; ++i) m = fmaxf(m, r1[i]);
        float sc = fmaxf(m, 1e-5f) * (1.0f / 127.0f);
        sh_s = sc;
        sh_inv = 1.0f / sc;
    }
    __syncthreads();
    const float inv = sh_inv;

    int q[8];
#pragma unroll
    for (int i = 0; i < 8; ++i)
        q[i] = (int)fminf(fmaxf(rintf(v[i] * inv), -127.f), 127.f);
    uint2 st;
    st.x = pack4(q[0], q[1], q[2], q[3]);
    st.y = pack4(q[4], q[5], q[6], q[7]);

    const int mt = t >> 7, r = t & 127;
    const int kc = tid >> 4, c = (tid >> 1) & 7, half = tid & 1;
    size_t off = ((size_t)(mt * NKT + kc) * 128 + r) * 128 +
                 (size_t)((c ^ (r & 7)) << 4) + (size_t)half * 8;
    *reinterpret_cast<uint2*>(g_Aq8 + off) = st;
    if (tid == 0) g_xscale[t] = sh_s;
}

// ---------------- Kernel 2: ternary int32 -> int8, same tiled layout
__global__ __launch_bounds__(256) void k_wconv(const int* __restrict__ wt) {
    const int n = blockIdx.x;
    const int tid = threadIdx.x;
    const int4* rp = reinterpret_cast<const int4*>(wt + (size_t)n * DIN);
    int4 a = rp[2 * tid], b = rp[2 * tid + 1];
    uint2 st;
    st.x = pack4(a.x, a.y, a.z, a.w);
    st.y = pack4(b.x, b.y, b.z, b.w);
    const int nt = n >> 7, r = n & 127;
    const int kc = tid >> 4, c = (tid >> 1) & 7, half = tid & 1;
    size_t off = ((size_t)(nt * NKT + kc) * 128 + r) * 128 +
                 (size_t)((c ^ (r & 7)) << 4) + (size_t)half * 8;
    *reinterpret_cast<uint2*>(g_Wq8 + off) = st;
}

// ---------------- Kernel 3: int8 IMMA GEMM, 128x128x128 tiles, 3-stage pipe,
// 2 CTAs/SM
__global__ __launch_bounds__(256, 2) void k_gemm(const float* __restrict__ wscale,
                                                 float* __restrict__ out) {
    extern __shared__ unsigned char smem[];
    const uint32_t sb = smem_u32(smem);
    const int tid = threadIdx.x, lane = tid & 31, wid = tid >> 5;
    const int bn = blockIdx.x, bm = blockIdx.y;

    // stage scales: ws at +512, xs at +1024
    if (tid < 128) {
        reinterpret_cast<float*>(smem + 512)[tid]  = wscale[bn * BNT + tid];
        reinterpret_cast<float*>(smem + 1024)[tid] = g_xscale[bm * BMT + tid];
    }
    if (tid == 0) {
#pragma unroll
        for (int s = 0; s < STAGES; ++s) {
            mbar_init(sb + 8 + 16 * s, 1);      // full[s]: tx-based
            mbar_init(sb + 16 + 16 * s, 256);   // empty[s]: all threads arrive
        }
        asm volatile("fence.proxy.async.shared::cta;" ::: "memory");
    }
    __syncthreads();

    const uint64_t gA = gptr(g_Aq8) + (uint64_t)bm * ((uint64_t)NKT * ATILE);
    const uint64_t gB = gptr(g_Wq8) + (uint64_t)bn * ((uint64_t)NKT * ATILE);

    if (tid == 0) {
#pragma unroll
        for (int s = 0; s < STAGES; ++s) {
            const uint32_t fb = sb + 8 + 16 * s;
            mbar_expect_tx(fb, STAGE_BYTES);
            bulk_g2s(sb + TILES_OFF + s * STAGE_BYTES,
                     gA + (uint64_t)s * ATILE, ATILE, fb);
            bulk_g2s(sb + TILES_OFF + s * STAGE_BYTES + ATILE,
                     gB + (uint64_t)s * ATILE, ATILE, fb);
        }
    }

    // warp grid 2x4: wm in M, wn in N
    const int wm = wid >> 2, wn = wid & 3;
    const int xr = lane & 7;
    const int hiA = lane >> 4;
    const int hiB = (lane >> 3) & 1;
    int rA[4], rB[2];
#pragma unroll
    for (int mt = 0; mt < 4; ++mt) rA[mt] = wm * 64 + mt * 16 + (lane & 15);
#pragma unroll
    for (int p = 0; p < 2; ++p)
        rB[p] = wn * 32 + p * 16 + ((lane >> 4) << 3) + (lane & 7);

    int C[4][4][4];
#pragma unroll
    for (int i = 0; i < 4; ++i)
#pragma unroll
        for (int j2 = 0; j2 < 4; ++j2)
#pragma unroll
            for (int k = 0; k < 4; ++k) C[i][j2][k] = 0;

    int s = 0, ph = 0;                       // stage cursor (mod 3 + parity)
    for (int kt = 0; kt < NKT; ++kt) {
        const uint32_t fb = sb + 8 + 16 * s;
        const uint32_t eb = sb + 16 + 16 * s;
        wait_parity(fb, (uint32_t)ph);
        const uint32_t aS = sb + TILES_OFF + s * STAGE_BYTES;
        const uint32_t bS = aS + ATILE;

#pragma unroll
        for (int ks = 0; ks < 4; ++ks) {
            uint32_t afr[4][4], bfr[2][4];
#pragma unroll
            for (int p = 0; p < 2; ++p) {
                uint32_t addr = bS + rB[p] * 128 +
                                (uint32_t)(((ks * 2 + hiB) ^ xr) << 4);
                LDSM4(bfr[p], addr);
            }
#pragma unroll
            for (int mt = 0; mt < 4; ++mt) {
                uint32_t addr = aS + rA[mt] * 128 +
                                (uint32_t)(((ks * 2 + hiA) ^ xr) << 4);
                LDSM4(afr[mt], addr);
            }
#pragma unroll
            for (int mt = 0; mt < 4; ++mt)
#pragma unroll
                for (int nt = 0; nt < 4; ++nt)
                    MMA_S8(C[mt][nt], afr[mt],
                           bfr[nt >> 1][(nt & 1) * 2],
                           bfr[nt >> 1][(nt & 1) * 2 + 1]);
        }
        mbar_arrive(eb);
        if (tid == 0 && kt + STAGES < NKT) {
            wait_parity(eb, (uint32_t)ph);   // all consumers done with stage s
            mbar_expect_tx(fb, STAGE_BYTES);
            bulk_g2s(aS, gA + (uint64_t)(kt + STAGES) * ATILE, ATILE, fb);
            bulk_g2s(bS, gB + (uint64_t)(kt + STAGES) * ATILE, ATILE, fb);
        }
        if (++s == STAGES) { s = 0; ph ^= 1; }
    }

    // epilogue: scale by xs[m] * ws[n], f32 stores
    const float* sws = reinterpret_cast<const float*>(smem + 512);
    const float* sxs = reinterpret_cast<const float*>(smem + 1024);
#pragma unroll
    for (int mt = 0; mt < 4; ++mt) {
        const int r0 = wm * 64 + mt * 16 + (lane >> 2);
        const float xs0 = sxs[r0], xs1 = sxs[r0 + 8];
#pragma unroll
        for (int nt = 0; nt < 4; ++nt) {
            const int col = wn * 32 + nt * 8 + ((lane & 3) << 1);
            const float w0 = sws[col], w1 = sws[col + 1];
            size_t base = (size_t)(bm * BMT + r0) * DOUT + (size_t)(bn * BNT + col);
            float2 o0, o1;
            o0.x = (float)C[mt][nt][0] * xs0 * w0;
            o0.y = (float)C[mt][nt][1] * xs0 * w1;
            o1.x = (float)C[mt][nt][2] * xs1 * w0;
            o1.y = (float)C[mt][nt][3] * xs1 * w1;
            *reinterpret_cast<float2*>(out + base) = o0;
            *reinterpret_cast<float2*>(out + base + 8 * DOUT) = o1;
        }
    }
}

// ---------------- Kernel 4: output LayerNorm in place
__global__ __launch_bounds__(256) void k_ln_out(float* __restrict__ out) {
    const int t = blockIdx.x;
    const int tid = threadIdx.x;
    const int lane = tid & 31, wid = tid >> 5;

    float4* rp = reinterpret_cast<float4*>(out + (size_t)t * DOUT);
    float4 p0 = rp[2 * tid], p1 = rp[2 * tid + 1];
    float v[8] = {p0.x, p0.y, p0.z, p0.w, p1.x, p1.y, p1.z, p1.w};

    float s = 0.f, sq = 0.f;
#pragma unroll
    for (int i = 0; i < 8; ++i) { s += v[i]; sq += v[i] * v[i]; }

    __shared__ float r1[8], r2[8];
    __shared__ float sh_mu, sh_rstd;
    s = warp_sum(s); sq = warp_sum(sq);
    if (lane == 0) { r1[wid] = s; r2[wid] = sq; }
    __syncthreads();
    if (tid == 0) {
        float a = 0.f, b = 0.f;
#pragma unroll
        for (int i = 0; i < 8; ++i) { a += r1[i]; b += r2[i]; }
        float mu = a * (1.0f / DOUT);
        float var = b * (1.0f / DOUT) - mu * mu;
        sh_mu = mu;
        sh_rstd = rsqrtf(var + 1e-5f);
    }
    __syncthreads();
    const float mu = sh_mu, rstd = sh_rstd;
    float4 q0, q1;
    q0.x = (v[0] - mu) * rstd; q0.y = (v[1] - mu) * rstd;
    q0.z = (v[2] - mu) * rstd; q0.w = (v[3] - mu) * rstd;
    q1.x = (v[4] - mu) * rstd; q1.y = (v[5] - mu) * rstd;
    q1.z = (v[6] - mu) * rstd; q1.w = (v[7] - mu) * rstd;
    rp[2 * tid] = q0; rp[2 * tid + 1] = q1;
}

extern "C" void kernel_launch(void* const* d_in, const int* in_sizes, int n_in,
                              void* d_out, int out_size) {
    const float* x = (const float*)d_in[0];
    const int* wt = (const int*)d_in[1];
    const float* ws = (const float*)d_in[2];
    float* out = (float*)d_out;

    cudaFuncSetAttribute(k_gemm, cudaFuncAttributeMaxDynamicSharedMemorySize,
                         GEMM_SMEM);

    k_ln_quant<<<NTOK, 256>>>(x);
    k_wconv<<<DOUT, 256>>>(wt);
    dim3 g(DOUT / BNT, NTOK / BMT);
    k_gemm<<<g, 256, GEMM_SMEM>>>(ws, out);
    k_ln_out<<<NTOK, 256>>>(out);
}

// round 8
// speedup vs baseline: 2.8953x; 2.7980x over previous
#include <cuda_runtime.h>
#include <cuda_bf16.h>
#include <cuda_fp16.h>
#include <cstdint>

// BitLinear158 on sm_103 (base ISA — harness ptxas rejects tcgen05):
//   LN -> int8 absmax quant (stored as f16) -> f16 HMMA GEMM (exact f32 accum)
//   -> xs*ws scale epilogue -> LN
// R7 EXPERIMENT: legacy HMMA vs the measured dp4a-emulation ceiling (77 TMAC/s).
// s8 IMMA baseline (991.6us) is banked; this discriminates instruction classes.

#define NTOK   16384
#define DIN    2048
#define DOUT   2048

#define BMT    128
#define BNT    128
#define KCH    64            // K elems per tile-chunk (64 f16 = 128 B rows)
#define NKT    (DIN / KCH)   // 32 K-chunks
#define STAGES 3
#define ATILE  16384         // 128 rows * 128 B per chunk
#define STAGE_BYTES (2 * ATILE)
#define TILES_OFF   2048
#define GEMM_SMEM   (TILES_OFF + STAGES * STAGE_BYTES)   // 100352 B -> 2 CTA/SM

__device__ __align__(1024) unsigned char g_Ah[(size_t)NTOK * DIN * 2];  // 64 MB
__device__ __align__(1024) unsigned char g_Wh[(size_t)DOUT * DIN * 2];  //  8 MB
__device__ float g_xscale[NTOK];

// ---------------- PTX helpers ----------------
__device__ __forceinline__ uint32_t smem_u32(const void* p) {
    uint32_t a;
    asm("{ .reg .u64 t; cvta.to.shared.u64 t, %1; cvt.u32.u64 %0, t; }"
        : "=r"(a) : "l"(p));
    return a;
}
__device__ __forceinline__ uint64_t gptr(const void* p) {
    uint64_t a;
    asm("cvta.to.global.u64 %0, %1;" : "=l"(a) : "l"(p));
    return a;
}
__device__ __forceinline__ void mbar_init(uint32_t mbar, uint32_t count) {
    asm volatile("mbarrier.init.shared.b64 [%0], %1;" :: "r"(mbar), "r"(count) : "memory");
}
__device__ __forceinline__ void mbar_expect_tx(uint32_t mbar, uint32_t bytes) {
    asm volatile("mbarrier.arrive.expect_tx.shared.b64 _, [%0], %1;"
                 :: "r"(mbar), "r"(bytes) : "memory");
}
__device__ __forceinline__ void mbar_arrive(uint32_t mbar) {
    asm volatile("mbarrier.arrive.shared.b64 _, [%0];" :: "r"(mbar) : "memory");
}
__device__ __forceinline__ void wait_parity(uint32_t mbar, uint32_t phase) {
    asm volatile(
        "{\n\t.reg .pred P;\n\t"
        "WL_%=:\n\t"
        "mbarrier.try_wait.parity.acquire.cta.shared::cta.b64 P, [%0], %1, 0x989680;\n\t"
        "@P bra.uni WD_%=;\n\t"
        "bra.uni WL_%=;\n\t"
        "WD_%=:\n\t}"
        :: "r"(mbar), "r"(phase) : "memory");
}
__device__ __forceinline__ void bulk_g2s(uint32_t dst, uint64_t src_global,
                                         uint32_t bytes, uint32_t mbar) {
    asm volatile(
        "cp.async.bulk.shared::cluster.global.mbarrier::complete_tx::bytes "
        "[%0], [%1], %2, [%3];"
        :: "r"(dst), "l"(src_global), "r"(bytes), "r"(mbar) : "memory");
}
#define LDSM4(d, addr) \
    asm volatile("ldmatrix.sync.aligned.m8n8.x4.shared.b16 {%0,%1,%2,%3}, [%4];" \
                 : "=r"((d)[0]), "=r"((d)[1]), "=r"((d)[2]), "=r"((d)[3])       \
                 : "r"(addr))
#define MMA_F16(C, A, b0, b1) \
    asm volatile("mma.sync.aligned.m16n8k16.row.col.f32.f16.f16.f32 "           \
                 "{%0,%1,%2,%3}, {%4,%5,%6,%7}, {%8,%9}, {%0,%1,%2,%3};"        \
                 : "+f"((C)[0]), "+f"((C)[1]), "+f"((C)[2]), "+f"((C)[3])       \
                 : "r"((A)[0]), "r"((A)[1]), "r"((A)[2]), "r"((A)[3]),          \
                   "r"(b0), "r"(b1))

__device__ __forceinline__ float warp_sum(float v) {
#pragma unroll
    for (int o = 16; o > 0; o >>= 1) v += __shfl_xor_sync(0xFFFFFFFFu, v, o);
    return v;
}
__device__ __forceinline__ float warp_max(float v) {
#pragma unroll
    for (int o = 16; o > 0; o >>= 1) v = fmaxf(v, __shfl_xor_sync(0xFFFFFFFFu, v, o));
    return v;
}
__device__ __forceinline__ uint32_t packh2(float a, float b) {
    __half2 h = __floats2half2_rn(a, b);
    return *reinterpret_cast<uint32_t*>(&h);
}

// ---------------- Kernel 1: input LN + absmax int8 quant -> f16 tiled scratch
// Warp per token. Values stored are exact small integers in f16.
__global__ __launch_bounds__(256) void k_ln_quant(const float* __restrict__ x) {
    const int t = blockIdx.x * 8 + (threadIdx.x >> 5);
    const int lane = threadIdx.x & 31;

    const float4* rp = reinterpret_cast<const float4*>(x + (size_t)t * DIN);
    float4 v[16];
#pragma unroll
    for (int i = 0; i < 16; ++i) v[i] = rp[lane + 32 * i];

    float s = 0.f, sq = 0.f;
#pragma unroll
    for (int i = 0; i < 16; ++i) {
        s += v[i].x + v[i].y + v[i].z + v[i].w;
        sq += v[i].x * v[i].x + v[i].y * v[i].y +
              v[i].z * v[i].z + v[i].w * v[i].w;
    }
    s = warp_sum(s); sq = warp_sum(sq);
    const float mu = s * (1.0f / DIN);
    const float var = sq * (1.0f / DIN) - mu * mu;
    const float rstd = rsqrtf(var + 1e-5f);

    float am = 0.f;
#pragma unroll
    for (int i = 0; i < 16; ++i) {
        am = fmaxf(am, fabsf(v[i].x - mu));
        am = fmaxf(am, fabsf(v[i].y - mu));
        am = fmaxf(am, fabsf(v[i].z - mu));
        am = fmaxf(am, fabsf(v[i].w - mu));
    }
    am = warp_max(am) * rstd;
    const float sc = fmaxf(am, 1e-5f) * (1.0f / 127.0f);
    const float f = rstd / sc;

    const int mt = t >> 7, r = t & 127;
    // element k0 = 4*lane + 128*i -> chunk kc = (lane>>4) + 2*i,
    // 16B-subchunk c16 = (lane&15)>>1, byte-in-subchunk = 8*(lane&1)
    const int c16 = (lane & 15) >> 1;
    const uint32_t swoff = (uint32_t)(((c16 ^ (r & 7)) << 4) | ((lane & 1) << 3));
    const size_t base = ((size_t)(mt * NKT) * 128 + r) * 128 + swoff +
                        (size_t)(lane >> 4) * ATILE;
#pragma unroll
    for (int i = 0; i < 16; ++i) {
        float q0 = fminf(fmaxf(rintf((v[i].x - mu) * f), -127.f), 127.f);
        float q1 = fminf(fmaxf(rintf((v[i].y - mu) * f), -127.f), 127.f);
        float q2 = fminf(fmaxf(rintf((v[i].z - mu) * f), -127.f), 127.f);
        float q3 = fminf(fmaxf(rintf((v[i].w - mu) * f), -127.f), 127.f);
        uint2 st;
        st.x = packh2(q0, q1);
        st.y = packh2(q2, q3);
        *reinterpret_cast<uint2*>(g_Ah + base + (size_t)(2 * i) * ATILE) = st;
    }
    if (lane == 0) g_xscale[t] = sc;
}

// ---------------- Kernel 2: ternary int32 -> f16, same tiled layout
__global__ __launch_bounds__(256) void k_wconv(const int* __restrict__ wt) {
    const int n = blockIdx.x;
    const int tid = threadIdx.x;
    const int4* rp = reinterpret_cast<const int4*>(wt + (size_t)n * DIN);
    int4 a = rp[2 * tid], b = rp[2 * tid + 1];
    uint4 st;
    st.x = packh2((float)a.x, (float)a.y);
    st.y = packh2((float)a.z, (float)a.w);
    st.z = packh2((float)b.x, (float)b.y);
    st.w = packh2((float)b.z, (float)b.w);
    const int nt = n >> 7, r = n & 127;
    const int kc = tid >> 3, c16 = tid & 7;   // k0 = 8*tid
    size_t off = ((size_t)(nt * NKT + kc) * 128 + r) * 128 +
                 (size_t)((c16 ^ (r & 7)) << 4);
    *reinterpret_cast<uint4*>(g_Wh + off) = st;
}

// ---------------- Kernel 2.5: no-op spacer (ncu capture slot -> k_gemm)
__global__ void k_mid() {}

// ---------------- Kernel 3: f16 HMMA GEMM, 128x128 tiles, 64-K chunks,
// 3-stage bulk pipeline, 2 CTAs/SM
__global__ __launch_bounds__(256, 2) void k_gemm(const float* __restrict__ wscale,
                                                 float* __restrict__ out) {
    extern __shared__ unsigned char smem[];
    const uint32_t sb = smem_u32(smem);
    const int tid = threadIdx.x, lane = tid & 31, wid = tid >> 5;
    const int bn = blockIdx.x, bm = blockIdx.y;

    if (tid < 128) {
        reinterpret_cast<float*>(smem + 512)[tid]  = wscale[bn * BNT + tid];
        reinterpret_cast<float*>(smem + 1024)[tid] = g_xscale[bm * BMT + tid];
    }
    if (tid == 0) {
#pragma unroll
        for (int s = 0; s < STAGES; ++s) {
            mbar_init(sb + 8 + 16 * s, 1);      // full[s]: tx-based
            mbar_init(sb + 16 + 16 * s, 256);   // empty[s]: all threads arrive
        }
        asm volatile("fence.proxy.async.shared::cta;" ::: "memory");
    }
    __syncthreads();

    const uint64_t gA = gptr(g_Ah) + (uint64_t)bm * ((uint64_t)NKT * ATILE);
    const uint64_t gB = gptr(g_Wh) + (uint64_t)bn * ((uint64_t)NKT * ATILE);

    if (tid == 0) {
#pragma unroll
        for (int s = 0; s < STAGES; ++s) {
            const uint32_t fb = sb + 8 + 16 * s;
            mbar_expect_tx(fb, STAGE_BYTES);
            bulk_g2s(sb + TILES_OFF + s * STAGE_BYTES,
                     gA + (uint64_t)s * ATILE, ATILE, fb);
            bulk_g2s(sb + TILES_OFF + s * STAGE_BYTES + ATILE,
                     gB + (uint64_t)s * ATILE, ATILE, fb);
        }
    }

    // warp grid 2x4: wm in M (64 rows), wn in N (32 cols)
    const int wm = wid >> 2, wn = wid & 3;
    const int xr = lane & 7;
    const int hiA = lane >> 4;          // A: lanes 16-31 take k8-15 subchunk
    const int hiB = (lane >> 3) & 1;    // B: lanes 8-15 / 24-31 take k8-15
    int rA[4], rB[2];
#pragma unroll
    for (int mt = 0; mt < 4; ++mt) rA[mt] = wm * 64 + mt * 16 + (lane & 15);
#pragma unroll
    for (int p = 0; p < 2; ++p)
        rB[p] = wn * 32 + p * 16 + ((lane >> 4) << 3) + (lane & 7);

    float C[4][4][4];
#pragma unroll
    for (int i = 0; i < 4; ++i)
#pragma unroll
        for (int j2 = 0; j2 < 4; ++j2)
#pragma unroll
            for (int k = 0; k < 4; ++k) C[i][j2][k] = 0.f;

    int s = 0, ph = 0;
    for (int kt = 0; kt < NKT; ++kt) {
        const uint32_t fb = sb + 8 + 16 * s;
        const uint32_t eb = sb + 16 + 16 * s;
        wait_parity(fb, (uint32_t)ph);
        const uint32_t aS = sb + TILES_OFF + s * STAGE_BYTES;
        const uint32_t bS = aS + ATILE;

#pragma unroll
        for (int ks = 0; ks < 4; ++ks) {   // 4 x k16 substeps per 64-K chunk
            uint32_t afr[4][4], bfr[2][4];
#pragma unroll
            for (int p = 0; p < 2; ++p) {
                uint32_t addr = bS + rB[p] * 128 +
                                (uint32_t)(((ks * 2 + hiB) ^ xr) << 4);
                LDSM4(bfr[p], addr);
            }
#pragma unroll
            for (int mt = 0; mt < 4; ++mt) {
                uint32_t addr = aS + rA[mt] * 128 +
                                (uint32_t)(((ks * 2 + hiA) ^ xr) << 4);
                LDSM4(afr[mt], addr);
            }
#pragma unroll
            for (int mt = 0; mt < 4; ++mt)
#pragma unroll
                for (int nt = 0; nt < 4; ++nt)
                    MMA_F16(C[mt][nt], afr[mt],
                            bfr[nt >> 1][(nt & 1) * 2],
                            bfr[nt >> 1][(nt & 1) * 2 + 1]);
        }
        mbar_arrive(eb);
        if (tid == 0 && kt + STAGES < NKT) {
            wait_parity(eb, (uint32_t)ph);
            mbar_expect_tx(fb, STAGE_BYTES);
            bulk_g2s(aS, gA + (uint64_t)(kt + STAGES) * ATILE, ATILE, fb);
            bulk_g2s(bS, gB + (uint64_t)(kt + STAGES) * ATILE, ATILE, fb);
        }
        if (++s == STAGES) { s = 0; ph ^= 1; }
    }

    // epilogue: scale by xs[m] * ws[n], f32 stores
    const float* sws = reinterpret_cast<const float*>(smem + 512);
    const float* sxs = reinterpret_cast<const float*>(smem + 1024);
#pragma unroll
    for (int mt = 0; mt < 4; ++mt) {
        const int r0 = wm * 64 + mt * 16 + (lane >> 2);
        const float xs0 = sxs[r0], xs1 = sxs[r0 + 8];
#pragma unroll
        for (int nt = 0; nt < 4; ++nt) {
            const int col = wn * 32 + nt * 8 + ((lane & 3) << 1);
            const float w0 = sws[col], w1 = sws[col + 1];
            size_t base = (size_t)(bm * BMT + r0) * DOUT + (size_t)(bn * BNT + col);
            float2 o0, o1;
            o0.x = C[mt][nt][0] * xs0 * w0;
            o0.y = C[mt][nt][1] * xs0 * w1;
            o1.x = C[mt][nt][2] * xs1 * w0;
            o1.y = C[mt][nt][3] * xs1 * w1;
            *reinterpret_cast<float2*>(out + base) = o0;
            *reinterpret_cast<float2*>(out + base + 8 * DOUT) = o1;
        }
    }
}

// ---------------- Kernel 4: output LayerNorm in place (warp per token)
__global__ __launch_bounds__(256) void k_ln_out(float* __restrict__ out) {
    const int t = blockIdx.x * 8 + (threadIdx.x >> 5);
    const int lane = threadIdx.x & 31;

    float4* rp = reinterpret_cast<float4*>(out + (size_t)t * DOUT);
    float4 v[16];
#pragma unroll
    for (int i = 0; i < 16; ++i) v[i] = rp[lane + 32 * i];

    float s = 0.f, sq = 0.f;
#pragma unroll
    for (int i = 0; i < 16; ++i) {
        s += v[i].x + v[i].y + v[i].z + v[i].w;
        sq += v[i].x * v[i].x + v[i].y * v[i].y +
              v[i].z * v[i].z + v[i].w * v[i].w;
    }
    s = warp_sum(s); sq = warp_sum(sq);
    const float mu = s * (1.0f / DOUT);
    const float var = sq * (1.0f / DOUT) - mu * mu;
    const float rstd = rsqrtf(var + 1e-5f);

#pragma unroll
    for (int i = 0; i < 16; ++i) {
        v[i].x = (v[i].x - mu) * rstd;
        v[i].y = (v[i].y - mu) * rstd;
        v[i].z = (v[i].z - mu) * rstd;
        v[i].w = (v[i].w - mu) * rstd;
        rp[lane + 32 * i] = v[i];
    }
}

extern "C" void kernel_launch(void* const* d_in, const int* in_sizes, int n_in,
                              void* d_out, int out_size) {
    const float* x = (const float*)d_in[0];
    const int* wt = (const int*)d_in[1];
    const float* ws = (const float*)d_in[2];
    float* out = (float*)d_out;

    cudaFuncSetAttribute(k_gemm, cudaFuncAttributeMaxDynamicSharedMemorySize,
                         GEMM_SMEM);

    k_ln_quant<<<NTOK / 8, 256>>>(x);
    k_wconv<<<DOUT, 256>>>(wt);
    k_mid<<<1, 32>>>();                    // spacer: puts k_gemm at slot 4
    dim3 g(DOUT / BNT, NTOK / BMT);
    k_gemm<<<g, 256, GEMM_SMEM>>>(ws, out);
    k_ln_out<<<NTOK / 8, 256>>>(out);
}